// round 4
// baseline (speedup 1.0000x reference)
#include <cuda_runtime.h>
#include <cuda_bf16.h>

// Problem reduction:
//   The reference only uses attention probs via their row-sums, which are
//   softmax row-sums == 1 (+-1e-6). So:
//     tmp  = value @ Wv^T + bv          -> out2, out3
//     out1 = tmp   @ Wo^T + bo
//   q/k projections, scores, softmaxes are dead code at rel_err 1e-3.
//
// Shapes: value [4,1024,1024] -> A [M=4096, K=1024]; W [N=1024, K=1024] row-major.
// C[m][n] = sum_k A[m][k] * W[n][k] + bias[n]   (an "NT" GEMM: both K-contiguous).

#define BM 128
#define BN 128
#define BK 16
#define TM 8
#define TN 8
#define NTHREADS 256   // (BM/TM)*(BN/TN)

static __global__ __launch_bounds__(NTHREADS, 2)
void gemm_nt_bias_kernel(const float* __restrict__ A,    // [M][K]
                         const float* __restrict__ W,    // [N][K]
                         const float* __restrict__ bias, // [N]
                         float* __restrict__ C0,         // [M][N]
                         float* __restrict__ C1,         // optional second copy (may be null)
                         int M, int N, int K)
{
    __shared__ float As[BK][BM + 4];
    __shared__ float Bs[BK][BN + 4];

    const int tid = threadIdx.x;
    const int blockRow = blockIdx.y * BM;
    const int blockCol = blockIdx.x * BN;

    const int ty = tid / (BN / TN);   // 0..15
    const int tx = tid % (BN / TN);   // 0..15

    float acc[TM][TN];
    #pragma unroll
    for (int i = 0; i < TM; i++)
        #pragma unroll
        for (int j = 0; j < TN; j++)
            acc[i][j] = 0.0f;

    // Each k-step loads a 128x16 A tile and 128x16 W tile.
    // 128*16/4 = 512 float4 loads per tile; 256 threads -> 2 float4 each.
    for (int k0 = 0; k0 < K; k0 += BK) {
        #pragma unroll
        for (int l = 0; l < 2; l++) {
            int idx = tid + l * NTHREADS;      // 0..511
            int row = idx >> 2;                // 0..127
            int kq  = (idx & 3) << 2;          // 0,4,8,12
            float4 va = *reinterpret_cast<const float4*>(
                &A[(size_t)(blockRow + row) * K + k0 + kq]);
            As[kq + 0][row] = va.x;
            As[kq + 1][row] = va.y;
            As[kq + 2][row] = va.z;
            As[kq + 3][row] = va.w;
            float4 vb = *reinterpret_cast<const float4*>(
                &W[(size_t)(blockCol + row) * K + k0 + kq]);
            Bs[kq + 0][row] = vb.x;
            Bs[kq + 1][row] = vb.y;
            Bs[kq + 2][row] = vb.z;
            Bs[kq + 3][row] = vb.w;
        }
        __syncthreads();

        #pragma unroll
        for (int k = 0; k < BK; k++) {
            float ra[TM], rb[TN];
            #pragma unroll
            for (int i = 0; i < TM; i++) ra[i] = As[k][ty * TM + i];
            #pragma unroll
            for (int j = 0; j < TN; j++) rb[j] = Bs[k][tx * TN + j];
            #pragma unroll
            for (int i = 0; i < TM; i++)
                #pragma unroll
                for (int j = 0; j < TN; j++)
                    acc[i][j] = fmaf(ra[i], rb[j], acc[i][j]);
        }
        __syncthreads();
    }

    // Epilogue: add bias, write one or two destinations.
    #pragma unroll
    for (int i = 0; i < TM; i++) {
        int gr = blockRow + ty * TM + i;
        #pragma unroll
        for (int j = 0; j < TN; j += 4) {
            int gc = blockCol + tx * TN + j;
            float4 out;
            out.x = acc[i][j + 0] + bias[gc + 0];
            out.y = acc[i][j + 1] + bias[gc + 1];
            out.z = acc[i][j + 2] + bias[gc + 2];
            out.w = acc[i][j + 3] + bias[gc + 3];
            *reinterpret_cast<float4*>(&C0[(size_t)gr * N + gc]) = out;
            if (C1) *reinterpret_cast<float4*>(&C1[(size_t)gr * N + gc]) = out;
        }
    }
}

extern "C" void kernel_launch(void* const* d_in, const int* in_sizes, int n_in,
                              void* d_out, int out_size)
{
    // Input order (metadata): query, key, value, Wq, bq, Wk, bk, Wv, bv, Wo, bo
    const float* value = (const float*)d_in[2];
    const float* Wv    = (const float*)d_in[7];
    const float* bv    = (const float*)d_in[8];
    const float* Wo    = (const float*)d_in[9];
    const float* bo    = (const float*)d_in[10];

    const int M = 4096;   // b*n = 4*1024
    const int N = 1024;   // d_model
    const int K = 1024;   // d_model

    float* out1 = (float*)d_out;                       // (merged @ Wo^T + bo)
    float* out2 = out1 + (size_t)M * N;                // merged (p_ident path)
    float* out3 = out2 + (size_t)M * N;                // merged (p_rand path, row-sums ~ 1)

    dim3 grid(N / BN, M / BM);
    dim3 block(NTHREADS);

    // tmp = value @ Wv^T + bv  -> written to out2 and out3
    gemm_nt_bias_kernel<<<grid, block>>>(value, Wv, bv, out2, out3, M, N, K);
    // out1 = tmp @ Wo^T + bo
    gemm_nt_bias_kernel<<<grid, block>>>(out2, Wo, bo, out1, nullptr, M, N, K);
}

// round 7
// speedup vs baseline: 2.6032x; 2.6032x over previous
#include <cuda_runtime.h>
#include <cuda_bf16.h>
#include <cstdint>
#include <cstddef>

// ============================================================================
// Reduction (verified R0-R4, rel_err 8e-7):
//   tmp  = value @ Wv^T + bv   -> out2, out3
//   out1 = tmp   @ Wo^T + bo
// tcgen05 is NOT available under the harness's compute_103 virtual target, so
// this round uses sm_80-class mma.sync m16n8k16 bf16 (legacy HMMA pipe) with
// the bf16x2 operand split:  A.B ~= Ah.Bh + Ah.Bl + Al.Bh  (err ~2^-18).
// ============================================================================

#define MDIM 4096
#define NDIM 1024
#define KDIM 1024

#define BM 128
#define BN 256
#define BK 32
#define NTHREADS 256      // 8 warps: 2 (m) x 4 (n), warp tile 64x64
#define NCHUNK (KDIM / BK) // 32

// smem: per stage, 4 tiles with 64B rows (BK=32 bf16)
#define AH_OFF 0
#define AL_OFF (BM * 64)                  // 8192
#define BH_OFF (2 * BM * 64)              // 16384
#define BL_OFF (2 * BM * 64 + BN * 64)    // 32768
#define STAGE_BYTES (2 * BM * 64 + 2 * BN * 64)   // 49152
#define SMEM_TOTAL (2 * STAGE_BYTES)              // 98304

// ---------------- device scratch (no runtime alloc allowed) ----------------
__device__ __nv_bfloat16 g_Ah[MDIM * KDIM];
__device__ __nv_bfloat16 g_Al[MDIM * KDIM];
__device__ __nv_bfloat16 g_TH[MDIM * KDIM];
__device__ __nv_bfloat16 g_TL[MDIM * KDIM];
__device__ __nv_bfloat16 g_WvH[NDIM * KDIM];
__device__ __nv_bfloat16 g_WvL[NDIM * KDIM];
__device__ __nv_bfloat16 g_WoH[NDIM * KDIM];
__device__ __nv_bfloat16 g_WoL[NDIM * KDIM];

// ---------------- PTX helpers (all plain-target legal, sm_80+) -------------
__device__ __forceinline__ uint32_t smem_u32(const void* p) {
    uint32_t a;
    asm("{ .reg .u64 t; cvta.to.shared.u64 t, %1; cvt.u32.u64 %0, t; }" : "=r"(a) : "l"(p));
    return a;
}
__device__ __forceinline__ void cp_async16(uint32_t dst, const void* src) {
    asm volatile("cp.async.cg.shared.global [%0], [%1], 16;" :: "r"(dst), "l"(src));
}
#define CP_COMMIT() asm volatile("cp.async.commit_group;")
#define CP_WAIT1()  asm volatile("cp.async.wait_group 1;")
#define CP_WAIT0()  asm volatile("cp.async.wait_group 0;")

__device__ __forceinline__ void ldsm_x4(uint32_t* r, uint32_t addr) {
    asm volatile("ldmatrix.sync.aligned.m8n8.x4.shared.b16 {%0,%1,%2,%3}, [%4];"
                 : "=r"(r[0]), "=r"(r[1]), "=r"(r[2]), "=r"(r[3]) : "r"(addr));
}
__device__ __forceinline__ void ldsm_x2(uint32_t* r, uint32_t addr) {
    asm volatile("ldmatrix.sync.aligned.m8n8.x2.shared.b16 {%0,%1}, [%2];"
                 : "=r"(r[0]), "=r"(r[1]) : "r"(addr));
}
__device__ __forceinline__ void mma_bf16(float* d, const uint32_t* a, const uint32_t* b) {
    asm volatile(
        "mma.sync.aligned.m16n8k16.row.col.f32.bf16.bf16.f32 "
        "{%0,%1,%2,%3}, {%4,%5,%6,%7}, {%8,%9}, {%0,%1,%2,%3};"
        : "+f"(d[0]), "+f"(d[1]), "+f"(d[2]), "+f"(d[3])
        : "r"(a[0]), "r"(a[1]), "r"(a[2]), "r"(a[3]), "r"(b[0]), "r"(b[1]));
}

// swizzle: 64B rows, 4 x 16B chunks; chunk' = chunk ^ ((row>>1)&3)
__device__ __forceinline__ uint32_t swz(int row, int chunk) {
    return (uint32_t)(row * 64 + ((chunk ^ ((row >> 1) & 3)) << 4));
}

// ---------------- split kernel: fp32 -> (bf16 hi, bf16 lo) ----------------
__global__ void split_bf16x2_kernel(const float4* __restrict__ x,
                                    uint2* __restrict__ hi,
                                    uint2* __restrict__ lo)
{
    int i = blockIdx.x * blockDim.x + threadIdx.x;
    float4 v = x[i];
    __nv_bfloat16 h0 = __float2bfloat16_rn(v.x);
    __nv_bfloat16 h1 = __float2bfloat16_rn(v.y);
    __nv_bfloat16 h2 = __float2bfloat16_rn(v.z);
    __nv_bfloat16 h3 = __float2bfloat16_rn(v.w);
    __nv_bfloat16 l0 = __float2bfloat16_rn(v.x - __bfloat162float(h0));
    __nv_bfloat16 l1 = __float2bfloat16_rn(v.y - __bfloat162float(h1));
    __nv_bfloat16 l2 = __float2bfloat16_rn(v.z - __bfloat162float(h2));
    __nv_bfloat16 l3 = __float2bfloat16_rn(v.w - __bfloat162float(h3));
    uint2 H, L;
    H.x = (uint32_t)__bfloat16_as_ushort(h0) | ((uint32_t)__bfloat16_as_ushort(h1) << 16);
    H.y = (uint32_t)__bfloat16_as_ushort(h2) | ((uint32_t)__bfloat16_as_ushort(h3) << 16);
    L.x = (uint32_t)__bfloat16_as_ushort(l0) | ((uint32_t)__bfloat16_as_ushort(l1) << 16);
    L.y = (uint32_t)__bfloat16_as_ushort(l2) | ((uint32_t)__bfloat16_as_ushort(l3) << 16);
    hi[i] = H;
    lo[i] = L;
}

// ---------------- bf16x2 split-GEMM on mma.sync (HMMA) ----------------
// C[m][n] = sum_k A[m][k] * W[n][k] + bias[n]
__global__ __launch_bounds__(NTHREADS, 1)
void gemm_bf16x2_mma_kernel(const __nv_bfloat16* __restrict__ Ah,
                            const __nv_bfloat16* __restrict__ Al,
                            const __nv_bfloat16* __restrict__ Bh,
                            const __nv_bfloat16* __restrict__ Bl,
                            const float* __restrict__ bias,
                            float* __restrict__ C0,
                            float* __restrict__ C1,
                            __nv_bfloat16* __restrict__ TH,
                            __nv_bfloat16* __restrict__ TL)
{
    extern __shared__ char smem[];
    const uint32_t sbase = smem_u32(smem);
    const int tid  = threadIdx.x;
    const int wid  = tid >> 5;
    const int lane = tid & 31;

    const int blockRow = blockIdx.y * BM;   // M
    const int blockCol = blockIdx.x * BN;   // N

    const int mbase = (wid & 1) * 64;       // warp m offset in CTA tile
    const int nbase = (wid >> 1) * 64;      // warp n offset

    const char* gAh = (const char*)Ah + (size_t)blockRow * (KDIM * 2);
    const char* gAl = (const char*)Al + (size_t)blockRow * (KDIM * 2);
    const char* gBh = (const char*)Bh + (size_t)blockCol * (KDIM * 2);
    const char* gBl = (const char*)Bl + (size_t)blockCol * (KDIM * 2);

    auto prefetch = [&](int c, int stage) {
        const uint32_t sb = sbase + stage * STAGE_BYTES;
        const size_t kb = (size_t)c * 64;    // BK=32 bf16 = 64 bytes along K
        #pragma unroll
        for (int t = 0; t < 2; t++) {        // A: 128 rows x 4 chunks = 512
            int i = tid + t * NTHREADS;
            int r = i >> 2, ch = i & 3;
            uint32_t sw = swz(r, ch);
            size_t g = (size_t)r * (KDIM * 2) + kb + ch * 16;
            cp_async16(sb + AH_OFF + sw, gAh + g);
            cp_async16(sb + AL_OFF + sw, gAl + g);
        }
        #pragma unroll
        for (int t = 0; t < 4; t++) {        // B: 256 rows x 4 chunks = 1024
            int i = tid + t * NTHREADS;
            int r = i >> 2, ch = i & 3;
            uint32_t sw = swz(r, ch);
            size_t g = (size_t)r * (KDIM * 2) + kb + ch * 16;
            cp_async16(sb + BH_OFF + sw, gBh + g);
            cp_async16(sb + BL_OFF + sw, gBl + g);
        }
        CP_COMMIT();
    };

    float acc[4][8][4];
    #pragma unroll
    for (int mi = 0; mi < 4; mi++)
        #pragma unroll
        for (int ni = 0; ni < 8; ni++)
            #pragma unroll
            for (int j = 0; j < 4; j++)
                acc[mi][ni][j] = 0.0f;

    prefetch(0, 0);
    prefetch(1, 1);

    // ldmatrix lane-derived row/chunk selectors
    const int a_rowsel = lane & 15;          // rows m..m+15
    const int a_csel   = lane >> 4;          // 0: k0-7, 1: k8-15
    const int b_rowsel = lane & 7;           // rows n..n+7
    const int b_csel   = (lane >> 3) & 1;

    for (int c = 0; c < NCHUNK; c++) {
        if (c < NCHUNK - 1) { CP_WAIT1(); } else { CP_WAIT0(); }
        __syncthreads();

        const uint32_t sb = sbase + (c & 1) * STAGE_BYTES;
        const uint32_t aH = sb + AH_OFF, aL = sb + AL_OFF;
        const uint32_t bH = sb + BH_OFF, bL = sb + BL_OFF;

        #pragma unroll
        for (int ks = 0; ks < 2; ks++) {
            uint32_t ah[4][4], bh[8][2];
            #pragma unroll
            for (int mi = 0; mi < 4; mi++) {
                int mrow = mbase + mi * 16 + a_rowsel;
                ldsm_x4(ah[mi], aH + swz(mrow, 2 * ks + a_csel));
            }
            #pragma unroll
            for (int ni = 0; ni < 8; ni++) {
                int nrow = nbase + ni * 8 + b_rowsel;
                ldsm_x2(bh[ni], bH + swz(nrow, 2 * ks + b_csel));
            }
            // pass 1: Ah * Bh
            #pragma unroll
            for (int mi = 0; mi < 4; mi++)
                #pragma unroll
                for (int ni = 0; ni < 8; ni++)
                    mma_bf16(acc[mi][ni], ah[mi], bh[ni]);
            // pass 2: Ah * Bl
            {
                uint32_t bl[8][2];
                #pragma unroll
                for (int ni = 0; ni < 8; ni++) {
                    int nrow = nbase + ni * 8 + b_rowsel;
                    ldsm_x2(bl[ni], bL + swz(nrow, 2 * ks + b_csel));
                }
                #pragma unroll
                for (int mi = 0; mi < 4; mi++)
                    #pragma unroll
                    for (int ni = 0; ni < 8; ni++)
                        mma_bf16(acc[mi][ni], ah[mi], bl[ni]);
            }
            // pass 3: Al * Bh
            {
                uint32_t al[4][4];
                #pragma unroll
                for (int mi = 0; mi < 4; mi++) {
                    int mrow = mbase + mi * 16 + a_rowsel;
                    ldsm_x4(al[mi], aL + swz(mrow, 2 * ks + a_csel));
                }
                #pragma unroll
                for (int mi = 0; mi < 4; mi++)
                    #pragma unroll
                    for (int ni = 0; ni < 8; ni++)
                        mma_bf16(acc[mi][ni], al[mi], bh[ni]);
            }
        }
        __syncthreads();
        if (c + 2 < NCHUNK) prefetch(c + 2, c & 1);
    }

    // ---------------- epilogue ----------------
    // c frag: lane t: rows (t/4, t/4+8), cols 2*(t%4)+{0,1}
    const int erow = lane >> 2;
    const int ecol = 2 * (lane & 3);
    #pragma unroll
    for (int mi = 0; mi < 4; mi++) {
        #pragma unroll
        for (int ni = 0; ni < 8; ni++) {
            int gr0 = blockRow + mbase + mi * 16 + erow;
            int gc  = blockCol + nbase + ni * 8 + ecol;
            float b0 = bias[gc], b1 = bias[gc + 1];
            float2 v0 = { acc[mi][ni][0] + b0, acc[mi][ni][1] + b1 };
            float2 v1 = { acc[mi][ni][2] + b0, acc[mi][ni][3] + b1 };
            size_t o0 = (size_t)gr0 * NDIM + gc;
            size_t o1 = (size_t)(gr0 + 8) * NDIM + gc;
            *(float2*)(C0 + o0) = v0;
            *(float2*)(C0 + o1) = v1;
            if (C1) {
                *(float2*)(C1 + o0) = v0;
                *(float2*)(C1 + o1) = v1;
            }
            if (TH) {
                __nv_bfloat16 h0 = __float2bfloat16_rn(v0.x);
                __nv_bfloat16 h1 = __float2bfloat16_rn(v0.y);
                __nv_bfloat16 h2 = __float2bfloat16_rn(v1.x);
                __nv_bfloat16 h3 = __float2bfloat16_rn(v1.y);
                uint32_t H0 = (uint32_t)__bfloat16_as_ushort(h0) | ((uint32_t)__bfloat16_as_ushort(h1) << 16);
                uint32_t H1 = (uint32_t)__bfloat16_as_ushort(h2) | ((uint32_t)__bfloat16_as_ushort(h3) << 16);
                __nv_bfloat16 l0 = __float2bfloat16_rn(v0.x - __bfloat162float(h0));
                __nv_bfloat16 l1 = __float2bfloat16_rn(v0.y - __bfloat162float(h1));
                __nv_bfloat16 l2 = __float2bfloat16_rn(v1.x - __bfloat162float(h2));
                __nv_bfloat16 l3 = __float2bfloat16_rn(v1.y - __bfloat162float(h3));
                uint32_t L0 = (uint32_t)__bfloat16_as_ushort(l0) | ((uint32_t)__bfloat16_as_ushort(l1) << 16);
                uint32_t L1 = (uint32_t)__bfloat16_as_ushort(l2) | ((uint32_t)__bfloat16_as_ushort(l3) << 16);
                *(uint32_t*)(TH + o0) = H0;
                *(uint32_t*)(TH + o1) = H1;
                *(uint32_t*)(TL + o0) = L0;
                *(uint32_t*)(TL + o1) = L1;
            }
        }
    }
}

// ---------------- launch ----------------
extern "C" void kernel_launch(void* const* d_in, const int* in_sizes, int n_in,
                              void* d_out, int out_size)
{
    // Inputs: query, key, value, Wq, bq, Wk, bk, Wv, bv, Wo, bo
    const float* value = (const float*)d_in[2];
    const float* Wv    = (const float*)d_in[7];
    const float* bv    = (const float*)d_in[8];
    const float* Wo    = (const float*)d_in[9];
    const float* bo    = (const float*)d_in[10];

    float* out1 = (float*)d_out;
    float* out2 = out1 + (size_t)MDIM * NDIM;
    float* out3 = out2 + (size_t)MDIM * NDIM;

    void *pAh, *pAl, *pTH, *pTL, *pWvH, *pWvL, *pWoH, *pWoL;
    cudaGetSymbolAddress(&pAh,  g_Ah);
    cudaGetSymbolAddress(&pAl,  g_Al);
    cudaGetSymbolAddress(&pTH,  g_TH);
    cudaGetSymbolAddress(&pTL,  g_TL);
    cudaGetSymbolAddress(&pWvH, g_WvH);
    cudaGetSymbolAddress(&pWvL, g_WvL);
    cudaGetSymbolAddress(&pWoH, g_WoH);
    cudaGetSymbolAddress(&pWoL, g_WoL);

    cudaFuncSetAttribute(gemm_bf16x2_mma_kernel,
                         cudaFuncAttributeMaxDynamicSharedMemorySize, SMEM_TOTAL);

    // splits: 4 elems/thread, 256 thr/blk
    split_bf16x2_kernel<<<(MDIM * KDIM) / 1024, 256>>>(
        (const float4*)value, (uint2*)pAh, (uint2*)pAl);
    split_bf16x2_kernel<<<(NDIM * KDIM) / 1024, 256>>>(
        (const float4*)Wv, (uint2*)pWvH, (uint2*)pWvL);
    split_bf16x2_kernel<<<(NDIM * KDIM) / 1024, 256>>>(
        (const float4*)Wo, (uint2*)pWoH, (uint2*)pWoL);

    dim3 grid(NDIM / BN, MDIM / BM);   // 4 x 32 = 128 CTAs (single wave)

    // GEMM1: tmp = value @ Wv^T + bv -> out2, out3 + bf16x2 split into TH/TL
    gemm_bf16x2_mma_kernel<<<grid, NTHREADS, SMEM_TOTAL>>>(
        (const __nv_bfloat16*)pAh, (const __nv_bfloat16*)pAl,
        (const __nv_bfloat16*)pWvH, (const __nv_bfloat16*)pWvL,
        bv, out2, out3, (__nv_bfloat16*)pTH, (__nv_bfloat16*)pTL);

    // GEMM2: out1 = tmp @ Wo^T + bo
    gemm_bf16x2_mma_kernel<<<grid, NTHREADS, SMEM_TOTAL>>>(
        (const __nv_bfloat16*)pTH, (const __nv_bfloat16*)pTL,
        (const __nv_bfloat16*)pWoH, (const __nv_bfloat16*)pWoL,
        bo, out1, nullptr, nullptr, nullptr);
}

// round 10
// speedup vs baseline: 2.7006x; 1.0374x over previous
#include <cuda_runtime.h>
#include <cuda_bf16.h>
#include <cstdint>
#include <cstddef>

// ============================================================================
// Reduction (verified, rel_err ~9e-6):
//   tmp  = value @ Wv^T + bv   -> out2, out3
//   out1 = tmp   @ Wo^T + bo
// bf16x2 split on mma.sync m16n8k16 (A.B ~= Ah.Bh + Ah.Bl + Al.Bh).
// R7 -> R8: 16 warps (warp tile 64x32, acc 64 regs), 3-stage cp.async ring
// with ONE __syncthreads per chunk. Goal: tensor pipe 52% -> ~80%.
// ============================================================================

#define MDIM 4096
#define NDIM 1024
#define KDIM 1024

#define BM 128
#define BN 256
#define BK 32
#define NTHREADS 512       // 16 warps: 2 (m) x 8 (n), warp tile 64x32
#define NCHUNK (KDIM / BK) // 32
#define NSTAGE 3

// smem per stage: A tiles 128 rows x 64B, B tiles 256 rows x 64B (h + l each)
#define AH_OFF 0
#define AL_OFF (BM * 64)                  // 8192
#define BH_OFF (2 * BM * 64)              // 16384
#define BL_OFF (2 * BM * 64 + BN * 64)    // 32768
#define STAGE_BYTES (2 * BM * 64 + 2 * BN * 64)   // 49152
#define SMEM_TOTAL (NSTAGE * STAGE_BYTES)         // 147456

// ---------------- device scratch (no runtime alloc allowed) ----------------
__device__ __nv_bfloat16 g_Ah[MDIM * KDIM];
__device__ __nv_bfloat16 g_Al[MDIM * KDIM];
__device__ __nv_bfloat16 g_TH[MDIM * KDIM];
__device__ __nv_bfloat16 g_TL[MDIM * KDIM];
__device__ __nv_bfloat16 g_WvH[NDIM * KDIM];
__device__ __nv_bfloat16 g_WvL[NDIM * KDIM];
__device__ __nv_bfloat16 g_WoH[NDIM * KDIM];
__device__ __nv_bfloat16 g_WoL[NDIM * KDIM];

// ---------------- PTX helpers (plain-target legal, sm_80+) -----------------
__device__ __forceinline__ uint32_t smem_u32(const void* p) {
    uint32_t a;
    asm("{ .reg .u64 t; cvta.to.shared.u64 t, %1; cvt.u32.u64 %0, t; }" : "=r"(a) : "l"(p));
    return a;
}
__device__ __forceinline__ void cp_async16(uint32_t dst, const void* src) {
    asm volatile("cp.async.cg.shared.global [%0], [%1], 16;" :: "r"(dst), "l"(src));
}
#define CP_COMMIT() asm volatile("cp.async.commit_group;")
#define CP_WAIT1()  asm volatile("cp.async.wait_group 1;")
#define CP_WAIT0()  asm volatile("cp.async.wait_group 0;")

__device__ __forceinline__ void ldsm_x4(uint32_t* r, uint32_t addr) {
    asm volatile("ldmatrix.sync.aligned.m8n8.x4.shared.b16 {%0,%1,%2,%3}, [%4];"
                 : "=r"(r[0]), "=r"(r[1]), "=r"(r[2]), "=r"(r[3]) : "r"(addr));
}
__device__ __forceinline__ void ldsm_x2(uint32_t* r, uint32_t addr) {
    asm volatile("ldmatrix.sync.aligned.m8n8.x2.shared.b16 {%0,%1}, [%2];"
                 : "=r"(r[0]), "=r"(r[1]) : "r"(addr));
}
__device__ __forceinline__ void mma_bf16(float* d, const uint32_t* a, const uint32_t* b) {
    asm volatile(
        "mma.sync.aligned.m16n8k16.row.col.f32.bf16.bf16.f32 "
        "{%0,%1,%2,%3}, {%4,%5,%6,%7}, {%8,%9}, {%0,%1,%2,%3};"
        : "+f"(d[0]), "+f"(d[1]), "+f"(d[2]), "+f"(d[3])
        : "r"(a[0]), "r"(a[1]), "r"(a[2]), "r"(a[3]), "r"(b[0]), "r"(b[1]));
}

// swizzle: 64B rows, 4 x 16B chunks; chunk' = chunk ^ ((row>>1)&3)
__device__ __forceinline__ uint32_t swz(int row, int chunk) {
    return (uint32_t)(row * 64 + ((chunk ^ ((row >> 1) & 3)) << 4));
}

// ---------------- split kernel: fp32 -> (bf16 hi, bf16 lo) ----------------
__global__ void split_bf16x2_kernel(const float4* __restrict__ x,
                                    uint2* __restrict__ hi,
                                    uint2* __restrict__ lo)
{
    int i = blockIdx.x * blockDim.x + threadIdx.x;
    float4 v = x[i];
    __nv_bfloat16 h0 = __float2bfloat16_rn(v.x);
    __nv_bfloat16 h1 = __float2bfloat16_rn(v.y);
    __nv_bfloat16 h2 = __float2bfloat16_rn(v.z);
    __nv_bfloat16 h3 = __float2bfloat16_rn(v.w);
    __nv_bfloat16 l0 = __float2bfloat16_rn(v.x - __bfloat162float(h0));
    __nv_bfloat16 l1 = __float2bfloat16_rn(v.y - __bfloat162float(h1));
    __nv_bfloat16 l2 = __float2bfloat16_rn(v.z - __bfloat162float(h2));
    __nv_bfloat16 l3 = __float2bfloat16_rn(v.w - __bfloat162float(h3));
    uint2 H, L;
    H.x = (uint32_t)__bfloat16_as_ushort(h0) | ((uint32_t)__bfloat16_as_ushort(h1) << 16);
    H.y = (uint32_t)__bfloat16_as_ushort(h2) | ((uint32_t)__bfloat16_as_ushort(h3) << 16);
    L.x = (uint32_t)__bfloat16_as_ushort(l0) | ((uint32_t)__bfloat16_as_ushort(l1) << 16);
    L.y = (uint32_t)__bfloat16_as_ushort(l2) | ((uint32_t)__bfloat16_as_ushort(l3) << 16);
    hi[i] = H;
    lo[i] = L;
}

// ---------------- bf16x2 split-GEMM on mma.sync (HMMA) ----------------
// C[m][n] = sum_k A[m][k] * W[n][k] + bias[n]
__global__ __launch_bounds__(NTHREADS, 1)
void gemm_bf16x2_mma_kernel(const __nv_bfloat16* __restrict__ Ah,
                            const __nv_bfloat16* __restrict__ Al,
                            const __nv_bfloat16* __restrict__ Bh,
                            const __nv_bfloat16* __restrict__ Bl,
                            const float* __restrict__ bias,
                            float* __restrict__ C0,
                            float* __restrict__ C1,
                            __nv_bfloat16* __restrict__ TH,
                            __nv_bfloat16* __restrict__ TL)
{
    extern __shared__ char smem[];
    const uint32_t sbase = smem_u32(smem);
    const int tid  = threadIdx.x;
    const int wid  = tid >> 5;
    const int lane = tid & 31;

    const int blockRow = blockIdx.y * BM;   // M
    const int blockCol = blockIdx.x * BN;   // N

    const int mbase = (wid & 1) * 64;       // warp m offset: 2 warps along M
    const int nbase = (wid >> 1) * 32;      // warp n offset: 8 warps along N

    const char* gAh = (const char*)Ah + (size_t)blockRow * (KDIM * 2);
    const char* gAl = (const char*)Al + (size_t)blockRow * (KDIM * 2);
    const char* gBh = (const char*)Bh + (size_t)blockCol * (KDIM * 2);
    const char* gBl = (const char*)Bl + (size_t)blockCol * (KDIM * 2);

    auto prefetch = [&](int c, int stage) {
        const uint32_t sb = sbase + stage * STAGE_BYTES;
        const size_t kb = (size_t)c * 64;    // BK=32 bf16 = 64 bytes along K
        {                                     // A: 128 rows x 4 chunks = 512 = NTHREADS
            int r = tid >> 2, ch = tid & 3;
            uint32_t sw = swz(r, ch);
            size_t g = (size_t)r * (KDIM * 2) + kb + ch * 16;
            cp_async16(sb + AH_OFF + sw, gAh + g);
            cp_async16(sb + AL_OFF + sw, gAl + g);
        }
        #pragma unroll
        for (int t = 0; t < 2; t++) {        // B: 256 rows x 4 chunks = 1024
            int i = tid + t * NTHREADS;
            int r = i >> 2, ch = i & 3;
            uint32_t sw = swz(r, ch);
            size_t g = (size_t)r * (KDIM * 2) + kb + ch * 16;
            cp_async16(sb + BH_OFF + sw, gBh + g);
            cp_async16(sb + BL_OFF + sw, gBl + g);
        }
        CP_COMMIT();
    };

    float acc[4][4][4];
    #pragma unroll
    for (int mi = 0; mi < 4; mi++)
        #pragma unroll
        for (int ni = 0; ni < 4; ni++)
            #pragma unroll
            for (int j = 0; j < 4; j++)
                acc[mi][ni][j] = 0.0f;

    prefetch(0, 0);
    prefetch(1, 1);

    // ldmatrix lane-derived row/chunk selectors
    const int a_rowsel = lane & 15;          // rows m..m+15
    const int a_csel   = lane >> 4;          // 0: k0-7, 1: k8-15
    const int b_rowsel = lane & 7;           // rows n..n+7
    const int b_csel   = (lane >> 3) & 1;

    for (int c = 0; c < NCHUNK; c++) {
        // pending groups: chunks c, c+1 -> wait_group 1 completes chunk c
        if (c < NCHUNK - 1) { CP_WAIT1(); } else { CP_WAIT0(); }
        __syncthreads();
        // Safe to refill stage (c+2)%3 now: the barrier above proves every
        // warp finished reading chunk c-1, whose stage is (c+2)%3.
        if (c + 2 < NCHUNK) prefetch(c + 2, (c + 2) % NSTAGE);

        const uint32_t sb = sbase + (c % NSTAGE) * STAGE_BYTES;
        const uint32_t aH = sb + AH_OFF, aL = sb + AL_OFF;
        const uint32_t bH = sb + BH_OFF, bL = sb + BL_OFF;

        #pragma unroll
        for (int ks = 0; ks < 2; ks++) {
            uint32_t ah[4][4], al[4][4], bh[4][2], bl[4][2];
            #pragma unroll
            for (int mi = 0; mi < 4; mi++) {
                int mrow = mbase + mi * 16 + a_rowsel;
                uint32_t so = swz(mrow, 2 * ks + a_csel);
                ldsm_x4(ah[mi], aH + so);
                ldsm_x4(al[mi], aL + so);
            }
            #pragma unroll
            for (int ni = 0; ni < 4; ni++) {
                int nrow = nbase + ni * 8 + b_rowsel;
                uint32_t so = swz(nrow, 2 * ks + b_csel);
                ldsm_x2(bh[ni], bH + so);
                ldsm_x2(bl[ni], bL + so);
            }
            #pragma unroll
            for (int mi = 0; mi < 4; mi++)
                #pragma unroll
                for (int ni = 0; ni < 4; ni++)
                    mma_bf16(acc[mi][ni], ah[mi], bh[ni]);   // Ah*Bh
            #pragma unroll
            for (int mi = 0; mi < 4; mi++)
                #pragma unroll
                for (int ni = 0; ni < 4; ni++)
                    mma_bf16(acc[mi][ni], ah[mi], bl[ni]);   // Ah*Bl
            #pragma unroll
            for (int mi = 0; mi < 4; mi++)
                #pragma unroll
                for (int ni = 0; ni < 4; ni++)
                    mma_bf16(acc[mi][ni], al[mi], bh[ni]);   // Al*Bh
        }
        // no trailing barrier: next iteration's top barrier protects reuse
    }

    // ---------------- epilogue ----------------
    // c frag: lane t: rows (t/4, t/4+8), cols 2*(t%4)+{0,1}
    const int erow = lane >> 2;
    const int ecol = 2 * (lane & 3);
    #pragma unroll
    for (int mi = 0; mi < 4; mi++) {
        #pragma unroll
        for (int ni = 0; ni < 4; ni++) {
            int gr0 = blockRow + mbase + mi * 16 + erow;
            int gc  = blockCol + nbase + ni * 8 + ecol;
            float b0 = bias[gc], b1 = bias[gc + 1];
            float2 v0 = { acc[mi][ni][0] + b0, acc[mi][ni][1] + b1 };
            float2 v1 = { acc[mi][ni][2] + b0, acc[mi][ni][3] + b1 };
            size_t o0 = (size_t)gr0 * NDIM + gc;
            size_t o1 = (size_t)(gr0 + 8) * NDIM + gc;
            *(float2*)(C0 + o0) = v0;
            *(float2*)(C0 + o1) = v1;
            if (C1) {
                *(float2*)(C1 + o0) = v0;
                *(float2*)(C1 + o1) = v1;
            }
            if (TH) {
                __nv_bfloat16 h0 = __float2bfloat16_rn(v0.x);
                __nv_bfloat16 h1 = __float2bfloat16_rn(v0.y);
                __nv_bfloat16 h2 = __float2bfloat16_rn(v1.x);
                __nv_bfloat16 h3 = __float2bfloat16_rn(v1.y);
                uint32_t H0 = (uint32_t)__bfloat16_as_ushort(h0) | ((uint32_t)__bfloat16_as_ushort(h1) << 16);
                uint32_t H1 = (uint32_t)__bfloat16_as_ushort(h2) | ((uint32_t)__bfloat16_as_ushort(h3) << 16);
                __nv_bfloat16 l0 = __float2bfloat16_rn(v0.x - __bfloat162float(h0));
                __nv_bfloat16 l1 = __float2bfloat16_rn(v0.y - __bfloat162float(h1));
                __nv_bfloat16 l2 = __float2bfloat16_rn(v1.x - __bfloat162float(h2));
                __nv_bfloat16 l3 = __float2bfloat16_rn(v1.y - __bfloat162float(h3));
                uint32_t L0 = (uint32_t)__bfloat16_as_ushort(l0) | ((uint32_t)__bfloat16_as_ushort(l1) << 16);
                uint32_t L1 = (uint32_t)__bfloat16_as_ushort(l2) | ((uint32_t)__bfloat16_as_ushort(l3) << 16);
                *(uint32_t*)(TH + o0) = H0;
                *(uint32_t*)(TH + o1) = H1;
                *(uint32_t*)(TL + o0) = L0;
                *(uint32_t*)(TL + o1) = L1;
            }
        }
    }
}

// ---------------- launch ----------------
extern "C" void kernel_launch(void* const* d_in, const int* in_sizes, int n_in,
                              void* d_out, int out_size)
{
    // Inputs: query, key, value, Wq, bq, Wk, bk, Wv, bv, Wo, bo
    const float* value = (const float*)d_in[2];
    const float* Wv    = (const float*)d_in[7];
    const float* bv    = (const float*)d_in[8];
    const float* Wo    = (const float*)d_in[9];
    const float* bo    = (const float*)d_in[10];

    float* out1 = (float*)d_out;
    float* out2 = out1 + (size_t)MDIM * NDIM;
    float* out3 = out2 + (size_t)MDIM * NDIM;

    void *pAh, *pAl, *pTH, *pTL, *pWvH, *pWvL, *pWoH, *pWoL;
    cudaGetSymbolAddress(&pAh,  g_Ah);
    cudaGetSymbolAddress(&pAl,  g_Al);
    cudaGetSymbolAddress(&pTH,  g_TH);
    cudaGetSymbolAddress(&pTL,  g_TL);
    cudaGetSymbolAddress(&pWvH, g_WvH);
    cudaGetSymbolAddress(&pWvL, g_WvL);
    cudaGetSymbolAddress(&pWoH, g_WoH);
    cudaGetSymbolAddress(&pWoL, g_WoL);

    cudaFuncSetAttribute(gemm_bf16x2_mma_kernel,
                         cudaFuncAttributeMaxDynamicSharedMemorySize, SMEM_TOTAL);

    // splits: 4 elems/thread, 256 thr/blk
    split_bf16x2_kernel<<<(MDIM * KDIM) / 1024, 256>>>(
        (const float4*)value, (uint2*)pAh, (uint2*)pAl);
    split_bf16x2_kernel<<<(NDIM * KDIM) / 1024, 256>>>(
        (const float4*)Wv, (uint2*)pWvH, (uint2*)pWvL);
    split_bf16x2_kernel<<<(NDIM * KDIM) / 1024, 256>>>(
        (const float4*)Wo, (uint2*)pWoH, (uint2*)pWoL);

    dim3 grid(NDIM / BN, MDIM / BM);   // 4 x 32 = 128 CTAs (single wave)

    // GEMM1: tmp = value @ Wv^T + bv -> out2, out3 + bf16x2 split into TH/TL
    gemm_bf16x2_mma_kernel<<<grid, NTHREADS, SMEM_TOTAL>>>(
        (const __nv_bfloat16*)pAh, (const __nv_bfloat16*)pAl,
        (const __nv_bfloat16*)pWvH, (const __nv_bfloat16*)pWvL,
        bv, out2, out3, (__nv_bfloat16*)pTH, (__nv_bfloat16*)pTL);

    // GEMM2: out1 = tmp @ Wo^T + bo
    gemm_bf16x2_mma_kernel<<<grid, NTHREADS, SMEM_TOTAL>>>(
        (const __nv_bfloat16*)pTH, (const __nv_bfloat16*)pTL,
        (const __nv_bfloat16*)pWoH, (const __nv_bfloat16*)pWoL,
        bo, out1, nullptr, nullptr, nullptr);
}

// round 12
// speedup vs baseline: 5.9159x; 2.1906x over previous
#include <cuda_runtime.h>
#include <cuda_fp16.h>
#include <cstdint>
#include <cstddef>

// ============================================================================
// Reduction (verified):
//   tmp  = value @ Wv^T + bv   -> out2, out3
//   out1 = tmp   @ Wo^T + bo
// R10 -> R11: replace 3-pass bf16 split with SINGLE-PASS fp16 mma.sync
// (m16n8k16 f32.f16.f16.f32). fp16's 11 mantissa bits give aggregate
// rel_err ~2.5e-4 < 1e-3 threshold. 3x fewer MMAs, 2x less smem traffic.
// ============================================================================

#define MDIM 4096
#define NDIM 1024
#define KDIM 1024

#define BM 128
#define BN 256
#define BK 64              // 64 fp16 = 128B rows -> canonical SW128 swizzle
#define NTHREADS 512       // 16 warps: 2 (m) x 8 (n), warp tile 64x32
#define NCHUNK (KDIM / BK) // 16
#define NSTAGE 3

// smem per stage: A 128 rows x 128B = 16KB, B 256 rows x 128B = 32KB
#define A_OFF 0
#define B_OFF (BM * 128)                       // 16384
#define STAGE_BYTES (BM * 128 + BN * 128)      // 49152
#define SMEM_TOTAL (NSTAGE * STAGE_BYTES)      // 147456

// ---------------- device scratch (no runtime alloc allowed) ----------------
__device__ __half g_A[MDIM * KDIM];    // fp16(value)
__device__ __half g_T[MDIM * KDIM];    // fp16(tmp)
__device__ __half g_Wv[NDIM * KDIM];
__device__ __half g_Wo[NDIM * KDIM];

// ---------------- PTX helpers (plain-target legal, sm_80+) -----------------
__device__ __forceinline__ uint32_t smem_u32(const void* p) {
    uint32_t a;
    asm("{ .reg .u64 t; cvta.to.shared.u64 t, %1; cvt.u32.u64 %0, t; }" : "=r"(a) : "l"(p));
    return a;
}
__device__ __forceinline__ void cp_async16(uint32_t dst, const void* src) {
    asm volatile("cp.async.cg.shared.global [%0], [%1], 16;" :: "r"(dst), "l"(src));
}
#define CP_COMMIT() asm volatile("cp.async.commit_group;")
#define CP_WAIT1()  asm volatile("cp.async.wait_group 1;")
#define CP_WAIT0()  asm volatile("cp.async.wait_group 0;")

__device__ __forceinline__ void ldsm_x4(uint32_t* r, uint32_t addr) {
    asm volatile("ldmatrix.sync.aligned.m8n8.x4.shared.b16 {%0,%1,%2,%3}, [%4];"
                 : "=r"(r[0]), "=r"(r[1]), "=r"(r[2]), "=r"(r[3]) : "r"(addr));
}
__device__ __forceinline__ void mma_f16(float* d, const uint32_t* a, const uint32_t* b) {
    asm volatile(
        "mma.sync.aligned.m16n8k16.row.col.f32.f16.f16.f32 "
        "{%0,%1,%2,%3}, {%4,%5,%6,%7}, {%8,%9}, {%0,%1,%2,%3};"
        : "+f"(d[0]), "+f"(d[1]), "+f"(d[2]), "+f"(d[3])
        : "r"(a[0]), "r"(a[1]), "r"(a[2]), "r"(a[3]), "r"(b[0]), "r"(b[1]));
}

// SW128 swizzle on 128B rows: 16B chunk index XOR (row & 7)
__device__ __forceinline__ uint32_t swz(int row, int ch) {
    return (uint32_t)(row * 128 + ((ch ^ (row & 7)) << 4));
}

// ---------------- split kernel: fp32 -> fp16 ----------------
__global__ void cvt_fp16_kernel(const float4* __restrict__ x, uint2* __restrict__ h)
{
    int i = blockIdx.x * blockDim.x + threadIdx.x;
    float4 v = x[i];
    __half2 p0 = __floats2half2_rn(v.x, v.y);
    __half2 p1 = __floats2half2_rn(v.z, v.w);
    uint2 o;
    o.x = *(uint32_t*)&p0;
    o.y = *(uint32_t*)&p1;
    h[i] = o;
}

// ---------------- fp16 single-pass GEMM on mma.sync (HMMA) ----------------
// C[m][n] = sum_k A[m][k] * W[n][k] + bias[n]
__global__ __launch_bounds__(NTHREADS, 1)
void gemm_f16_mma_kernel(const __half* __restrict__ A,
                         const __half* __restrict__ B,
                         const float* __restrict__ bias,
                         float* __restrict__ C0,
                         float* __restrict__ C1,
                         __half* __restrict__ TH)
{
    extern __shared__ char smem[];
    const uint32_t sbase = smem_u32(smem);
    const int tid  = threadIdx.x;
    const int wid  = tid >> 5;
    const int lane = tid & 31;

    const int blockRow = blockIdx.y * BM;   // M
    const int blockCol = blockIdx.x * BN;   // N

    const int mbase = (wid & 1) * 64;       // 2 warps along M
    const int nbase = (wid >> 1) * 32;      // 8 warps along N

    const char* gA = (const char*)A + (size_t)blockRow * (KDIM * 2);
    const char* gB = (const char*)B + (size_t)blockCol * (KDIM * 2);

    auto prefetch = [&](int c, int stage) {
        const uint32_t sb = sbase + stage * STAGE_BYTES;
        const size_t kb = (size_t)c * 128;   // BK=64 fp16 = 128 bytes along K
        #pragma unroll
        for (int t = 0; t < 2; t++) {        // A: 128 rows x 8 chunks = 1024
            int i = tid + t * NTHREADS;
            int r = i >> 3, ch = i & 7;
            cp_async16(sb + A_OFF + swz(r, ch),
                       gA + (size_t)r * (KDIM * 2) + kb + ch * 16);
        }
        #pragma unroll
        for (int t = 0; t < 4; t++) {        // B: 256 rows x 8 chunks = 2048
            int i = tid + t * NTHREADS;
            int r = i >> 3, ch = i & 7;
            cp_async16(sb + B_OFF + swz(r, ch),
                       gB + (size_t)r * (KDIM * 2) + kb + ch * 16);
        }
        CP_COMMIT();
    };

    float acc[4][4][4];
    #pragma unroll
    for (int mi = 0; mi < 4; mi++)
        #pragma unroll
        for (int ni = 0; ni < 4; ni++)
            #pragma unroll
            for (int j = 0; j < 4; j++)
                acc[mi][ni][j] = 0.0f;

    prefetch(0, 0);
    prefetch(1, 1);

    // ldmatrix lane-derived selectors
    const int a_row = lane & 15;             // rows m..m+15 (2 matrices)
    const int a_ch  = lane >> 4;             // k-chunk 0/1 within ks
    const int b_row = lane & 7;              // rows n..n+7
    const int b_ch  = (lane >> 3) & 1;       // k-chunk 0/1
    const int b_nj  = lane >> 4;             // which of the 2 n-tiles

    for (int c = 0; c < NCHUNK; c++) {
        if (c < NCHUNK - 1) { CP_WAIT1(); } else { CP_WAIT0(); }
        __syncthreads();
        // stage (c+2)%3 held chunk c-1; barrier above proves readers done
        if (c + 2 < NCHUNK) prefetch(c + 2, (c + 2) % NSTAGE);

        const uint32_t sb = sbase + (c % NSTAGE) * STAGE_BYTES;
        const uint32_t aS = sb + A_OFF, bS = sb + B_OFF;

        #pragma unroll
        for (int ks = 0; ks < 4; ks++) {     // 4 x K=16 per chunk
            uint32_t ah[4][4], bh[4][2];
            #pragma unroll
            for (int mi = 0; mi < 4; mi++) {
                int mrow = mbase + mi * 16 + a_row;
                ldsm_x4(ah[mi], aS + swz(mrow, 2 * ks + a_ch));
            }
            #pragma unroll
            for (int nj = 0; nj < 2; nj++) { // each x4 covers 2 n-tiles
                uint32_t r4[4];
                int nrow = nbase + (nj * 2 + b_nj) * 8 + b_row;
                ldsm_x4(r4, bS + swz(nrow, 2 * ks + b_ch));
                bh[nj * 2 + 0][0] = r4[0]; bh[nj * 2 + 0][1] = r4[1];
                bh[nj * 2 + 1][0] = r4[2]; bh[nj * 2 + 1][1] = r4[3];
            }
            #pragma unroll
            for (int mi = 0; mi < 4; mi++)
                #pragma unroll
                for (int ni = 0; ni < 4; ni++)
                    mma_f16(acc[mi][ni], ah[mi], bh[ni]);
        }
    }

    // ---------------- epilogue ----------------
    // c frag: lane t -> rows (t/4, t/4+8), cols 2*(t%4)+{0,1}
    const int erow = lane >> 2;
    const int ecol = 2 * (lane & 3);
    #pragma unroll
    for (int mi = 0; mi < 4; mi++) {
        #pragma unroll
        for (int ni = 0; ni < 4; ni++) {
            int gr0 = blockRow + mbase + mi * 16 + erow;
            int gc  = blockCol + nbase + ni * 8 + ecol;
            float b0 = bias[gc], b1 = bias[gc + 1];
            float2 v0 = { acc[mi][ni][0] + b0, acc[mi][ni][1] + b1 };
            float2 v1 = { acc[mi][ni][2] + b0, acc[mi][ni][3] + b1 };
            size_t o0 = (size_t)gr0 * NDIM + gc;
            size_t o1 = (size_t)(gr0 + 8) * NDIM + gc;
            *(float2*)(C0 + o0) = v0;
            *(float2*)(C0 + o1) = v1;
            if (C1) {
                *(float2*)(C1 + o0) = v0;
                *(float2*)(C1 + o1) = v1;
            }
            if (TH) {
                __half2 h0 = __floats2half2_rn(v0.x, v0.y);
                __half2 h1 = __floats2half2_rn(v1.x, v1.y);
                *(__half2*)(TH + o0) = h0;
                *(__half2*)(TH + o1) = h1;
            }
        }
    }
}

// ---------------- launch ----------------
extern "C" void kernel_launch(void* const* d_in, const int* in_sizes, int n_in,
                              void* d_out, int out_size)
{
    // Inputs: query, key, value, Wq, bq, Wk, bk, Wv, bv, Wo, bo
    const float* value = (const float*)d_in[2];
    const float* Wv    = (const float*)d_in[7];
    const float* bv    = (const float*)d_in[8];
    const float* Wo    = (const float*)d_in[9];
    const float* bo    = (const float*)d_in[10];

    float* out1 = (float*)d_out;
    float* out2 = out1 + (size_t)MDIM * NDIM;
    float* out3 = out2 + (size_t)MDIM * NDIM;

    void *pA, *pT, *pWv, *pWo;
    cudaGetSymbolAddress(&pA,  g_A);
    cudaGetSymbolAddress(&pT,  g_T);
    cudaGetSymbolAddress(&pWv, g_Wv);
    cudaGetSymbolAddress(&pWo, g_Wo);

    cudaFuncSetAttribute(gemm_f16_mma_kernel,
                         cudaFuncAttributeMaxDynamicSharedMemorySize, SMEM_TOTAL);

    // fp32 -> fp16 conversions (4 elems/thread)
    cvt_fp16_kernel<<<(MDIM * KDIM) / 1024, 256>>>((const float4*)value, (uint2*)pA);
    cvt_fp16_kernel<<<(NDIM * KDIM) / 1024, 256>>>((const float4*)Wv, (uint2*)pWv);
    cvt_fp16_kernel<<<(NDIM * KDIM) / 1024, 256>>>((const float4*)Wo, (uint2*)pWo);

    dim3 grid(NDIM / BN, MDIM / BM);   // 4 x 32 = 128 CTAs (single wave)

    // GEMM1: tmp = value @ Wv^T + bv -> out2, out3 + fp16(tmp) into g_T
    gemm_f16_mma_kernel<<<grid, NTHREADS, SMEM_TOTAL>>>(
        (const __half*)pA, (const __half*)pWv, bv,
        out2, out3, (__half*)pT);

    // GEMM2: out1 = tmp @ Wo^T + bo
    gemm_f16_mma_kernel<<<grid, NTHREADS, SMEM_TOTAL>>>(
        (const __half*)pT, (const __half*)pWo, bo,
        out1, nullptr, nullptr);
}

// round 13
// speedup vs baseline: 5.9830x; 1.0113x over previous
#include <cuda_runtime.h>
#include <cuda_fp16.h>
#include <cstdint>
#include <cstddef>

// ============================================================================
// Reduction (verified):
//   tmp  = value @ Wv^T + bv   -> out2, out3
//   out1 = tmp   @ Wo^T + bo
// Single-pass fp16 mma.sync (rel_err ~4e-4 < 1e-3).
// R12 -> R13: BN 256->128, 256 threads, smem 96KB -> TWO CTAs per SM.
// Cross-CTA overlap hides barrier/cp.async stalls (tensor 41.6% -> ~65%).
// ============================================================================

#define MDIM 4096
#define NDIM 1024
#define KDIM 1024

#define BM 128
#define BN 128
#define BK 64              // 64 fp16 = 128B rows -> canonical SW128 swizzle
#define NTHREADS 256       // 8 warps: 2 (m) x 4 (n), warp tile 64x32
#define NCHUNK (KDIM / BK) // 16
#define NSTAGE 3

// smem per stage: A 128 rows x 128B = 16KB, B 128 rows x 128B = 16KB
#define A_OFF 0
#define B_OFF (BM * 128)                       // 16384
#define STAGE_BYTES (BM * 128 + BN * 128)      // 32768
#define SMEM_TOTAL (NSTAGE * STAGE_BYTES)      // 98304 -> 2 CTAs/SM

// ---------------- device scratch (no runtime alloc allowed) ----------------
__device__ __half g_A[MDIM * KDIM];    // fp16(value)
__device__ __half g_T[MDIM * KDIM];    // fp16(tmp)
__device__ __half g_Wv[NDIM * KDIM];
__device__ __half g_Wo[NDIM * KDIM];

// ---------------- PTX helpers (plain-target legal, sm_80+) -----------------
__device__ __forceinline__ uint32_t smem_u32(const void* p) {
    uint32_t a;
    asm("{ .reg .u64 t; cvta.to.shared.u64 t, %1; cvt.u32.u64 %0, t; }" : "=r"(a) : "l"(p));
    return a;
}
__device__ __forceinline__ void cp_async16(uint32_t dst, const void* src) {
    asm volatile("cp.async.cg.shared.global [%0], [%1], 16;" :: "r"(dst), "l"(src));
}
#define CP_COMMIT() asm volatile("cp.async.commit_group;")
#define CP_WAIT1()  asm volatile("cp.async.wait_group 1;")
#define CP_WAIT0()  asm volatile("cp.async.wait_group 0;")

__device__ __forceinline__ void ldsm_x4(uint32_t* r, uint32_t addr) {
    asm volatile("ldmatrix.sync.aligned.m8n8.x4.shared.b16 {%0,%1,%2,%3}, [%4];"
                 : "=r"(r[0]), "=r"(r[1]), "=r"(r[2]), "=r"(r[3]) : "r"(addr));
}
__device__ __forceinline__ void mma_f16(float* d, const uint32_t* a, const uint32_t* b) {
    asm volatile(
        "mma.sync.aligned.m16n8k16.row.col.f32.f16.f16.f32 "
        "{%0,%1,%2,%3}, {%4,%5,%6,%7}, {%8,%9}, {%0,%1,%2,%3};"
        : "+f"(d[0]), "+f"(d[1]), "+f"(d[2]), "+f"(d[3])
        : "r"(a[0]), "r"(a[1]), "r"(a[2]), "r"(a[3]), "r"(b[0]), "r"(b[1]));
}

// SW128 swizzle on 128B rows: 16B chunk index XOR (row & 7)
__device__ __forceinline__ uint32_t swz(int row, int ch) {
    return (uint32_t)(row * 128 + ((ch ^ (row & 7)) << 4));
}

// ---------------- convert kernel: fp32 -> fp16 ----------------
__global__ void cvt_fp16_kernel(const float4* __restrict__ x, uint2* __restrict__ h)
{
    int i = blockIdx.x * blockDim.x + threadIdx.x;
    float4 v = x[i];
    __half2 p0 = __floats2half2_rn(v.x, v.y);
    __half2 p1 = __floats2half2_rn(v.z, v.w);
    uint2 o;
    o.x = *(uint32_t*)&p0;
    o.y = *(uint32_t*)&p1;
    h[i] = o;
}

// ---------------- fp16 single-pass GEMM on mma.sync (HMMA) ----------------
// C[m][n] = sum_k A[m][k] * W[n][k] + bias[n]
__global__ __launch_bounds__(NTHREADS, 2)
void gemm_f16_mma_kernel(const __half* __restrict__ A,
                         const __half* __restrict__ B,
                         const float* __restrict__ bias,
                         float* __restrict__ C0,
                         float* __restrict__ C1,
                         __half* __restrict__ TH)
{
    extern __shared__ char smem[];
    const uint32_t sbase = smem_u32(smem);
    const int tid  = threadIdx.x;
    const int wid  = tid >> 5;
    const int lane = tid & 31;

    const int blockRow = blockIdx.y * BM;   // M
    const int blockCol = blockIdx.x * BN;   // N

    const int mbase = (wid & 1) * 64;       // 2 warps along M
    const int nbase = (wid >> 1) * 32;      // 4 warps along N

    const char* gA = (const char*)A + (size_t)blockRow * (KDIM * 2);
    const char* gB = (const char*)B + (size_t)blockCol * (KDIM * 2);

    auto prefetch = [&](int c, int stage) {
        const uint32_t sb = sbase + stage * STAGE_BYTES;
        const size_t kb = (size_t)c * 128;   // BK=64 fp16 = 128 bytes along K
        #pragma unroll
        for (int t = 0; t < 4; t++) {        // A: 128 rows x 8 chunks = 1024
            int i = tid + t * NTHREADS;
            int r = i >> 3, ch = i & 7;
            cp_async16(sb + A_OFF + swz(r, ch),
                       gA + (size_t)r * (KDIM * 2) + kb + ch * 16);
        }
        #pragma unroll
        for (int t = 0; t < 4; t++) {        // B: 128 rows x 8 chunks = 1024
            int i = tid + t * NTHREADS;
            int r = i >> 3, ch = i & 7;
            cp_async16(sb + B_OFF + swz(r, ch),
                       gB + (size_t)r * (KDIM * 2) + kb + ch * 16);
        }
        CP_COMMIT();
    };

    float acc[4][4][4];
    #pragma unroll
    for (int mi = 0; mi < 4; mi++)
        #pragma unroll
        for (int ni = 0; ni < 4; ni++)
            #pragma unroll
            for (int j = 0; j < 4; j++)
                acc[mi][ni][j] = 0.0f;

    prefetch(0, 0);
    prefetch(1, 1);

    // ldmatrix lane-derived selectors
    const int a_row = lane & 15;             // rows m..m+15 (2 matrices)
    const int a_ch  = lane >> 4;             // k-chunk 0/1 within ks
    const int b_row = lane & 7;              // rows n..n+7
    const int b_ch  = (lane >> 3) & 1;       // k-chunk 0/1
    const int b_nj  = lane >> 4;             // which of the 2 n-tiles

    for (int c = 0; c < NCHUNK; c++) {
        if (c < NCHUNK - 1) { CP_WAIT1(); } else { CP_WAIT0(); }
        __syncthreads();
        // stage (c+2)%3 held chunk c-1; barrier above proves readers done
        if (c + 2 < NCHUNK) prefetch(c + 2, (c + 2) % NSTAGE);

        const uint32_t sb = sbase + (c % NSTAGE) * STAGE_BYTES;
        const uint32_t aS = sb + A_OFF, bS = sb + B_OFF;

        #pragma unroll
        for (int ks = 0; ks < 4; ks++) {     // 4 x K=16 per chunk
            uint32_t ah[4][4], bh[4][2];
            #pragma unroll
            for (int mi = 0; mi < 4; mi++) {
                int mrow = mbase + mi * 16 + a_row;
                ldsm_x4(ah[mi], aS + swz(mrow, 2 * ks + a_ch));
            }
            #pragma unroll
            for (int nj = 0; nj < 2; nj++) { // each x4 covers 2 n-tiles
                uint32_t r4[4];
                int nrow = nbase + (nj * 2 + b_nj) * 8 + b_row;
                ldsm_x4(r4, bS + swz(nrow, 2 * ks + b_ch));
                bh[nj * 2 + 0][0] = r4[0]; bh[nj * 2 + 0][1] = r4[1];
                bh[nj * 2 + 1][0] = r4[2]; bh[nj * 2 + 1][1] = r4[3];
            }
            #pragma unroll
            for (int mi = 0; mi < 4; mi++)
                #pragma unroll
                for (int ni = 0; ni < 4; ni++)
                    mma_f16(acc[mi][ni], ah[mi], bh[ni]);
        }
    }

    // ---------------- epilogue ----------------
    // c frag: lane t -> rows (t/4, t/4+8), cols 2*(t%4)+{0,1}
    const int erow = lane >> 2;
    const int ecol = 2 * (lane & 3);
    #pragma unroll
    for (int mi = 0; mi < 4; mi++) {
        #pragma unroll
        for (int ni = 0; ni < 4; ni++) {
            int gr0 = blockRow + mbase + mi * 16 + erow;
            int gc  = blockCol + nbase + ni * 8 + ecol;
            float b0 = bias[gc], b1 = bias[gc + 1];
            float2 v0 = { acc[mi][ni][0] + b0, acc[mi][ni][1] + b1 };
            float2 v1 = { acc[mi][ni][2] + b0, acc[mi][ni][3] + b1 };
            size_t o0 = (size_t)gr0 * NDIM + gc;
            size_t o1 = (size_t)(gr0 + 8) * NDIM + gc;
            *(float2*)(C0 + o0) = v0;
            *(float2*)(C0 + o1) = v1;
            if (C1) {
                *(float2*)(C1 + o0) = v0;
                *(float2*)(C1 + o1) = v1;
            }
            if (TH) {
                __half2 h0 = __floats2half2_rn(v0.x, v0.y);
                __half2 h1 = __floats2half2_rn(v1.x, v1.y);
                *(__half2*)(TH + o0) = h0;
                *(__half2*)(TH + o1) = h1;
            }
        }
    }
}

// ---------------- launch ----------------
extern "C" void kernel_launch(void* const* d_in, const int* in_sizes, int n_in,
                              void* d_out, int out_size)
{
    // Inputs: query, key, value, Wq, bq, Wk, bk, Wv, bv, Wo, bo
    const float* value = (const float*)d_in[2];
    const float* Wv    = (const float*)d_in[7];
    const float* bv    = (const float*)d_in[8];
    const float* Wo    = (const float*)d_in[9];
    const float* bo    = (const float*)d_in[10];

    float* out1 = (float*)d_out;
    float* out2 = out1 + (size_t)MDIM * NDIM;
    float* out3 = out2 + (size_t)MDIM * NDIM;

    void *pA, *pT, *pWv, *pWo;
    cudaGetSymbolAddress(&pA,  g_A);
    cudaGetSymbolAddress(&pT,  g_T);
    cudaGetSymbolAddress(&pWv, g_Wv);
    cudaGetSymbolAddress(&pWo, g_Wo);

    cudaFuncSetAttribute(gemm_f16_mma_kernel,
                         cudaFuncAttributeMaxDynamicSharedMemorySize, SMEM_TOTAL);

    // fp32 -> fp16 conversions (4 elems/thread)
    cvt_fp16_kernel<<<(MDIM * KDIM) / 1024, 256>>>((const float4*)value, (uint2*)pA);
    cvt_fp16_kernel<<<(NDIM * KDIM) / 1024, 256>>>((const float4*)Wv, (uint2*)pWv);
    cvt_fp16_kernel<<<(NDIM * KDIM) / 1024, 256>>>((const float4*)Wo, (uint2*)pWo);

    dim3 grid(NDIM / BN, MDIM / BM);   // 8 x 32 = 256 CTAs (~2 per SM)

    // GEMM1: tmp = value @ Wv^T + bv -> out2, out3 + fp16(tmp) into g_T
    gemm_f16_mma_kernel<<<grid, NTHREADS, SMEM_TOTAL>>>(
        (const __half*)pA, (const __half*)pWv, bv,
        out2, out3, (__half*)pT);

    // GEMM2: out1 = tmp @ Wo^T + bo
    gemm_f16_mma_kernel<<<grid, NTHREADS, SMEM_TOTAL>>>(
        (const __half*)pT, (const __half*)pWo, bo,
        out1, nullptr, nullptr);
}

// round 14
// speedup vs baseline: 6.0838x; 1.0169x over previous
#include <cuda_runtime.h>
#include <cuda_fp16.h>
#include <cstdint>
#include <cstddef>

// ============================================================================
// Reduction (verified):
//   tmp  = value @ Wv^T + bv   -> out2, out3
//   out1 = tmp   @ Wo^T + bo
// Single-pass fp16 mma.sync (rel_err ~4e-4 < 1e-3).
// R13 -> R14: warp tile 64x32 -> 64x64 (LDSM per MMA: 192B -> 128B, halved
// instruction count), CTA 128x128 with 4 warps, 2 CTAs/SM, grid 256 = one
// fully-resident wave. Attack the LDSM/smem-bandwidth + issue mix.
// ============================================================================

#define MDIM 4096
#define NDIM 1024
#define KDIM 1024

#define BM 128
#define BN 128
#define BK 64              // 64 fp16 = 128B rows -> canonical SW128 swizzle
#define NTHREADS 128       // 4 warps: 2 (m) x 2 (n), warp tile 64x64
#define NCHUNK (KDIM / BK) // 16
#define NSTAGE 3

// smem per stage: A 128 rows x 128B = 16KB, B 128 rows x 128B = 16KB
#define A_OFF 0
#define B_OFF (BM * 128)                       // 16384
#define STAGE_BYTES (BM * 128 + BN * 128)      // 32768
#define SMEM_TOTAL (NSTAGE * STAGE_BYTES)      // 98304 -> 2 CTAs/SM

// ---------------- device scratch (no runtime alloc allowed) ----------------
__device__ __half g_A[MDIM * KDIM];    // fp16(value)
__device__ __half g_T[MDIM * KDIM];    // fp16(tmp)
__device__ __half g_Wv[NDIM * KDIM];
__device__ __half g_Wo[NDIM * KDIM];

// ---------------- PTX helpers (plain-target legal, sm_80+) -----------------
__device__ __forceinline__ uint32_t smem_u32(const void* p) {
    uint32_t a;
    asm("{ .reg .u64 t; cvta.to.shared.u64 t, %1; cvt.u32.u64 %0, t; }" : "=r"(a) : "l"(p));
    return a;
}
__device__ __forceinline__ void cp_async16(uint32_t dst, const void* src) {
    asm volatile("cp.async.cg.shared.global [%0], [%1], 16;" :: "r"(dst), "l"(src));
}
#define CP_COMMIT() asm volatile("cp.async.commit_group;")
#define CP_WAIT1()  asm volatile("cp.async.wait_group 1;")
#define CP_WAIT0()  asm volatile("cp.async.wait_group 0;")

__device__ __forceinline__ void ldsm_x4(uint32_t* r, uint32_t addr) {
    asm volatile("ldmatrix.sync.aligned.m8n8.x4.shared.b16 {%0,%1,%2,%3}, [%4];"
                 : "=r"(r[0]), "=r"(r[1]), "=r"(r[2]), "=r"(r[3]) : "r"(addr));
}
__device__ __forceinline__ void mma_f16(float* d, const uint32_t* a, const uint32_t* b) {
    asm volatile(
        "mma.sync.aligned.m16n8k16.row.col.f32.f16.f16.f32 "
        "{%0,%1,%2,%3}, {%4,%5,%6,%7}, {%8,%9}, {%0,%1,%2,%3};"
        : "+f"(d[0]), "+f"(d[1]), "+f"(d[2]), "+f"(d[3])
        : "r"(a[0]), "r"(a[1]), "r"(a[2]), "r"(a[3]), "r"(b[0]), "r"(b[1]));
}

// SW128 swizzle on 128B rows: 16B chunk index XOR (row & 7)
__device__ __forceinline__ uint32_t swz(int row, int ch) {
    return (uint32_t)(row * 128 + ((ch ^ (row & 7)) << 4));
}

// ---------------- convert kernel: fp32 -> fp16 ----------------
__global__ void cvt_fp16_kernel(const float4* __restrict__ x, uint2* __restrict__ h)
{
    int i = blockIdx.x * blockDim.x + threadIdx.x;
    float4 v = x[i];
    __half2 p0 = __floats2half2_rn(v.x, v.y);
    __half2 p1 = __floats2half2_rn(v.z, v.w);
    uint2 o;
    o.x = *(uint32_t*)&p0;
    o.y = *(uint32_t*)&p1;
    h[i] = o;
}

// ---------------- fp16 single-pass GEMM on mma.sync (HMMA) ----------------
// C[m][n] = sum_k A[m][k] * W[n][k] + bias[n]
__global__ __launch_bounds__(NTHREADS, 2)
void gemm_f16_mma_kernel(const __half* __restrict__ A,
                         const __half* __restrict__ B,
                         const float* __restrict__ bias,
                         float* __restrict__ C0,
                         float* __restrict__ C1,
                         __half* __restrict__ TH)
{
    extern __shared__ char smem[];
    const uint32_t sbase = smem_u32(smem);
    const int tid  = threadIdx.x;
    const int wid  = tid >> 5;
    const int lane = tid & 31;

    const int blockRow = blockIdx.y * BM;   // M
    const int blockCol = blockIdx.x * BN;   // N

    const int mbase = (wid & 1) * 64;       // 2 warps along M
    const int nbase = (wid >> 1) * 64;      // 2 warps along N, warp tile 64x64

    const char* gA = (const char*)A + (size_t)blockRow * (KDIM * 2);
    const char* gB = (const char*)B + (size_t)blockCol * (KDIM * 2);

    auto prefetch = [&](int c, int stage) {
        const uint32_t sb = sbase + stage * STAGE_BYTES;
        const size_t kb = (size_t)c * 128;   // BK=64 fp16 = 128 bytes along K
        #pragma unroll
        for (int t = 0; t < 8; t++) {        // A: 128 rows x 8 chunks = 1024
            int i = tid + t * NTHREADS;
            int r = i >> 3, ch = i & 7;
            cp_async16(sb + A_OFF + swz(r, ch),
                       gA + (size_t)r * (KDIM * 2) + kb + ch * 16);
        }
        #pragma unroll
        for (int t = 0; t < 8; t++) {        // B: 128 rows x 8 chunks = 1024
            int i = tid + t * NTHREADS;
            int r = i >> 3, ch = i & 7;
            cp_async16(sb + B_OFF + swz(r, ch),
                       gB + (size_t)r * (KDIM * 2) + kb + ch * 16);
        }
        CP_COMMIT();
    };

    float acc[4][8][4];
    #pragma unroll
    for (int mi = 0; mi < 4; mi++)
        #pragma unroll
        for (int ni = 0; ni < 8; ni++)
            #pragma unroll
            for (int j = 0; j < 4; j++)
                acc[mi][ni][j] = 0.0f;

    prefetch(0, 0);
    prefetch(1, 1);

    // ldmatrix lane-derived selectors
    const int a_row = lane & 15;             // rows m..m+15 (2 matrices)
    const int a_ch  = lane >> 4;             // k-chunk 0/1 within ks
    const int b_row = lane & 7;              // rows n..n+7
    const int b_ch  = (lane >> 3) & 1;       // k-chunk 0/1
    const int b_nj  = lane >> 4;             // which of the 2 n-tiles in an x4

    for (int c = 0; c < NCHUNK; c++) {
        if (c < NCHUNK - 1) { CP_WAIT1(); } else { CP_WAIT0(); }
        __syncthreads();
        // stage (c+2)%3 held chunk c-1; barrier above proves readers done
        if (c + 2 < NCHUNK) prefetch(c + 2, (c + 2) % NSTAGE);

        const uint32_t sb = sbase + (c % NSTAGE) * STAGE_BYTES;
        const uint32_t aS = sb + A_OFF, bS = sb + B_OFF;

        #pragma unroll
        for (int ks = 0; ks < 4; ks++) {     // 4 x K=16 per chunk
            uint32_t ah[4][4], bh[8][2];
            #pragma unroll
            for (int mi = 0; mi < 4; mi++) {
                int mrow = mbase + mi * 16 + a_row;
                ldsm_x4(ah[mi], aS + swz(mrow, 2 * ks + a_ch));
            }
            #pragma unroll
            for (int nj = 0; nj < 4; nj++) { // each x4 covers 2 n-tiles
                uint32_t r4[4];
                int nrow = nbase + (nj * 2 + b_nj) * 8 + b_row;
                ldsm_x4(r4, bS + swz(nrow, 2 * ks + b_ch));
                bh[nj * 2 + 0][0] = r4[0]; bh[nj * 2 + 0][1] = r4[1];
                bh[nj * 2 + 1][0] = r4[2]; bh[nj * 2 + 1][1] = r4[3];
            }
            #pragma unroll
            for (int mi = 0; mi < 4; mi++)
                #pragma unroll
                for (int ni = 0; ni < 8; ni++)
                    mma_f16(acc[mi][ni], ah[mi], bh[ni]);
        }
    }

    // ---------------- epilogue ----------------
    // c frag: lane t -> rows (t/4, t/4+8), cols 2*(t%4)+{0,1}
    const int erow = lane >> 2;
    const int ecol = 2 * (lane & 3);
    #pragma unroll
    for (int mi = 0; mi < 4; mi++) {
        #pragma unroll
        for (int ni = 0; ni < 8; ni++) {
            int gr0 = blockRow + mbase + mi * 16 + erow;
            int gc  = blockCol + nbase + ni * 8 + ecol;
            float b0 = bias[gc], b1 = bias[gc + 1];
            float2 v0 = { acc[mi][ni][0] + b0, acc[mi][ni][1] + b1 };
            float2 v1 = { acc[mi][ni][2] + b0, acc[mi][ni][3] + b1 };
            size_t o0 = (size_t)gr0 * NDIM + gc;
            size_t o1 = (size_t)(gr0 + 8) * NDIM + gc;
            *(float2*)(C0 + o0) = v0;
            *(float2*)(C0 + o1) = v1;
            if (C1) {
                *(float2*)(C1 + o0) = v0;
                *(float2*)(C1 + o1) = v1;
            }
            if (TH) {
                __half2 h0 = __floats2half2_rn(v0.x, v0.y);
                __half2 h1 = __floats2half2_rn(v1.x, v1.y);
                *(__half2*)(TH + o0) = h0;
                *(__half2*)(TH + o1) = h1;
            }
        }
    }
}

// ---------------- launch ----------------
extern "C" void kernel_launch(void* const* d_in, const int* in_sizes, int n_in,
                              void* d_out, int out_size)
{
    // Inputs: query, key, value, Wq, bq, Wk, bk, Wv, bv, Wo, bo
    const float* value = (const float*)d_in[2];
    const float* Wv    = (const float*)d_in[7];
    const float* bv    = (const float*)d_in[8];
    const float* Wo    = (const float*)d_in[9];
    const float* bo    = (const float*)d_in[10];

    float* out1 = (float*)d_out;
    float* out2 = out1 + (size_t)MDIM * NDIM;
    float* out3 = out2 + (size_t)MDIM * NDIM;

    void *pA, *pT, *pWv, *pWo;
    cudaGetSymbolAddress(&pA,  g_A);
    cudaGetSymbolAddress(&pT,  g_T);
    cudaGetSymbolAddress(&pWv, g_Wv);
    cudaGetSymbolAddress(&pWo, g_Wo);

    cudaFuncSetAttribute(gemm_f16_mma_kernel,
                         cudaFuncAttributeMaxDynamicSharedMemorySize, SMEM_TOTAL);

    // fp32 -> fp16 conversions (4 elems/thread)
    cvt_fp16_kernel<<<(MDIM * KDIM) / 1024, 256>>>((const float4*)value, (uint2*)pA);
    cvt_fp16_kernel<<<(NDIM * KDIM) / 1024, 256>>>((const float4*)Wv, (uint2*)pWv);
    cvt_fp16_kernel<<<(NDIM * KDIM) / 1024, 256>>>((const float4*)Wo, (uint2*)pWo);

    dim3 grid(NDIM / BN, MDIM / BM);   // 8 x 32 = 256 CTAs, all resident (2/SM)

    // GEMM1: tmp = value @ Wv^T + bv -> out2, out3 + fp16(tmp) into g_T
    gemm_f16_mma_kernel<<<grid, NTHREADS, SMEM_TOTAL>>>(
        (const __half*)pA, (const __half*)pWv, bv,
        out2, out3, (__half*)pT);

    // GEMM2: out1 = tmp @ Wo^T + bo
    gemm_f16_mma_kernel<<<grid, NTHREADS, SMEM_TOTAL>>>(
        (const __half*)pT, (const __half*)pWo, bo,
        out1, nullptr, nullptr);
}